// round 6
// baseline (speedup 1.0000x reference)
#include <cuda_runtime.h>
#include <cstdint>
#include <math.h>

#define Bb 2
#define Nn 2048
#define Mm 2048
#define DIMd 512
#define Hh 8
#define DHd 64
#define INNERi 512

// ---------------- scratch (allocation-free) ----------------
__device__ float g_q[Bb * Nn * INNERi];
__device__ float g_k[Bb * Mm * INNERi];
__device__ float g_v[Bb * Nn * INNERi];
__device__ float g_ctx[Bb * Nn * INNERi];
__device__ float g_wqvt[2 * INNERi * DIMd];
__device__ float g_wkt[INNERi * DIMd];
__device__ float g_wot[DIMd * INNERi];

// ---------------- helpers ----------------
__device__ __forceinline__ float to_tf32(float x) {
    uint32_t r;
    asm("cvt.rna.tf32.f32 %0, %1;" : "=r"(r) : "f"(x));
    return __uint_as_float(r);
}
__device__ __forceinline__ uint32_t to_tf32u(float x) {
    uint32_t r;
    asm("cvt.rna.tf32.f32 %0, %1;" : "=r"(r) : "f"(x));
    return r;
}
__device__ __forceinline__ void mma8(float* c, uint32_t a0, uint32_t a1,
                                     uint32_t a2, uint32_t a3, uint32_t b0,
                                     uint32_t b1) {
    asm volatile(
        "mma.sync.aligned.m16n8k8.row.col.f32.tf32.tf32.f32 "
        "{%0,%1,%2,%3}, {%4,%5,%6,%7}, {%8,%9}, {%0,%1,%2,%3};"
        : "+f"(c[0]), "+f"(c[1]), "+f"(c[2]), "+f"(c[3])
        : "r"(a0), "r"(a1), "r"(a2), "r"(a3), "r"(b0), "r"(b1));
}
#define FAU(x) __float_as_uint(x)
#define CPA16(dst, src) \
    asm volatile("cp.async.cg.shared.global [%0], [%1], 16;" ::"r"(dst), "l"(src))
#define CP_COMMIT() asm volatile("cp.async.commit_group;")

// ---------------- batched W transpose + tf32 round (one launch) ------------
// seg 0: Wqv [512][1024] -> wqvt [1024][512]   blocks 0..511
// seg 1: Wk  [512][512]  -> wkt  [512][512]    blocks 512..767
// seg 2: Wout[512][512]  -> wot  [512][512]    blocks 768..1023
__global__ __launch_bounds__(256) void transposeAll(
    const float* __restrict__ Wqv, const float* __restrict__ Wk,
    const float* __restrict__ Wout, float* __restrict__ wqvt,
    float* __restrict__ wkt, float* __restrict__ wot) {
    __shared__ float t[32][33];
    int bid = blockIdx.x;
    const float* W;
    float* Wt;
    int N, bloc;
    if (bid < 512) { W = Wqv; Wt = wqvt; N = 1024; bloc = bid; }
    else if (bid < 768) { W = Wk; Wt = wkt; N = 512; bloc = bid - 512; }
    else { W = Wout; Wt = wot; N = 512; bloc = bid - 768; }
    const int K = 512;
    int nb = N / 32;
    int n0 = (bloc % nb) * 32, k0 = (bloc / nb) * 32;
    int x = threadIdx.x & 31, y = threadIdx.x >> 5;
#pragma unroll
    for (int i = 0; i < 32; i += 8) t[y + i][x] = W[(size_t)(k0 + y + i) * N + n0 + x];
    __syncthreads();
#pragma unroll
    for (int i = 0; i < 32; i += 8)
        Wt[(size_t)(n0 + y + i) * K + k0 + x] = to_tf32(t[x][y + i]);
}

// ---------------- mma.sync tf32 GEMM: C[Rows x Cols] = A[Rows x K] @ Wt[Cols x K]^T
// A is raw f32 (tf32-rounded at fragment load); Wt pre-rounded.
// MODE 0: plain, output tf32-rounded (k proj)
// MODE 1: qv split -> cols<512 to C0, else C1 (both ld 512), tf32-rounded
// MODE 2: + bias, plain f32 output (final out)
template <int MODE>
__global__ __launch_bounds__(256) void mma_gemm(
    const float* __restrict__ A, const float* __restrict__ Wt,
    float* __restrict__ C0, float* __restrict__ C1,
    const float* __restrict__ bias, int Cols, int Kd) {
    extern __shared__ float sm[];
    const int tid = threadIdx.x, lane = tid & 31, wid = tid >> 5;
    const int g = lane >> 2, t = lane & 3;
    const int warp_m = wid & 1, warp_n = wid >> 1;
    const int row0 = blockIdx.y * 128, col0 = blockIdx.x * 128;
    const uint32_t smb = (uint32_t)__cvta_generic_to_shared(sm);

    float acc[4][4][4];
#pragma unroll
    for (int i = 0; i < 4; i++)
#pragma unroll
        for (int j = 0; j < 4; j++)
#pragma unroll
            for (int q = 0; q < 4; q++) acc[i][j][q] = 0.f;

    const int nch = Kd / 32;
    auto issue = [&](int c) {
        const int s = c & 1, k0 = c * 32;
        const uint32_t ab = smb + s * 9216 * 4;
        const uint32_t bb = ab + 4608 * 4;
#pragma unroll
        for (int p = 0; p < 4; p++) {
            int idx = tid + p * 256;
            int r = idx >> 3, c4 = idx & 7;
            CPA16(ab + (r * 36 + c4 * 4) * 4, &A[(size_t)(row0 + r) * Kd + k0 + c4 * 4]);
            CPA16(bb + (r * 36 + c4 * 4) * 4, &Wt[(size_t)(col0 + r) * Kd + k0 + c4 * 4]);
        }
        CP_COMMIT();
    };
    issue(0);
    issue(1);

    for (int c = 0; c < nch; c++) {
        if (c + 1 < nch) asm volatile("cp.async.wait_group 1;");
        else asm volatile("cp.async.wait_group 0;");
        __syncthreads();
        const float* As = sm + (c & 1) * 9216;
        const float* Bs = As + 4608;
#pragma unroll
        for (int ks = 0; ks < 4; ks++) {
            const int k0s = ks * 8;
            uint32_t af[4][4], bf[4][2];
#pragma unroll
            for (int mt = 0; mt < 4; mt++) {
                const float* ap = As + (warp_m * 64 + mt * 16 + g) * 36 + k0s + t;
                af[mt][0] = to_tf32u(ap[0]);
                af[mt][1] = to_tf32u(ap[8 * 36]);
                af[mt][2] = to_tf32u(ap[4]);
                af[mt][3] = to_tf32u(ap[8 * 36 + 4]);
            }
#pragma unroll
            for (int nt = 0; nt < 4; nt++) {
                const float* bp = Bs + (warp_n * 32 + nt * 8 + g) * 36 + k0s + t;
                bf[nt][0] = FAU(bp[0]);
                bf[nt][1] = FAU(bp[4]);
            }
#pragma unroll
            for (int mt = 0; mt < 4; mt++)
#pragma unroll
                for (int nt = 0; nt < 4; nt++)
                    mma8(acc[mt][nt], af[mt][0], af[mt][1], af[mt][2], af[mt][3],
                         bf[nt][0], bf[nt][1]);
        }
        __syncthreads();
        if (c + 2 < nch) issue(c + 2);
    }

    // epilogue
#pragma unroll
    for (int mt = 0; mt < 4; mt++) {
#pragma unroll
        for (int nt = 0; nt < 4; nt++) {
            const int r = row0 + warp_m * 64 + mt * 16 + g;
            const int cc = col0 + warp_n * 32 + nt * 8 + 2 * t;
            float v0 = acc[mt][nt][0], v1 = acc[mt][nt][1];
            float v2 = acc[mt][nt][2], v3 = acc[mt][nt][3];
            if (MODE == 2) {
                v0 += bias[cc];
                v1 += bias[cc + 1];
                v2 += bias[cc];
                v3 += bias[cc + 1];
            } else {
                v0 = to_tf32(v0);
                v1 = to_tf32(v1);
                v2 = to_tf32(v2);
                v3 = to_tf32(v3);
            }
            float* dst = C0;
            int c2 = cc, ld = Cols;
            if (MODE == 1) {
                dst = (cc < INNERi) ? C0 : C1;
                c2 = cc & (INNERi - 1);
                ld = INNERi;
            }
            float2 lo = {v0, v1}, hi = {v2, v3};
            *(float2*)&dst[(size_t)r * ld + c2] = lo;
            *(float2*)&dst[(size_t)(r + 8) * ld + c2] = hi;
        }
    }
}

// ---------------- fused attention with mma.sync tf32 ----------------
// block = 64 q-rows x (h, b); 128 threads (4 warps, 16 rows each).
// smem 87040 B -> 2 CTAs/SM with natural registers (softmax hides under MMA).
__global__ __launch_bounds__(128) void attn_mma(
    const float* __restrict__ q, const float* __restrict__ k,
    const float* __restrict__ v, const float* __restrict__ am,
    const float* __restrict__ dp, const float* __restrict__ mp,
    float* __restrict__ ctx) {
    extern __shared__ float sm[];
    // Ks: 2 x [64][68] @ 0 ; Vs: 2 x [64][68] @ 8704 floats ; Pq: [64][68] @ 17408
    float* Ks = sm;
    float* Vs = sm + 2 * 4352;
    float* Pq = sm + 4 * 4352;

    const int tid = threadIdx.x, lane = tid & 31, wid = tid >> 5;
    const int g = lane >> 2, t = lane & 3;
    const int n0 = blockIdx.x * 64;
    const int h = blockIdx.y, b = blockIdx.z;
    const int rw = wid * 16;
    const float sc = 0.125f * dp[0];
    const float mpv = mp[0];
    const uint32_t smb = (uint32_t)__cvta_generic_to_shared(sm);
    const uint32_t pqb = smb + 4 * 4352 * 4;

    // stage Q tile [64][64] into Pq
    {
        const float* qb = q + ((size_t)(b * Nn) + n0) * INNERi + h * DHd;
#pragma unroll
        for (int p = 0; p < 8; p++) {
            int idx = tid + p * 128;
            int r = idx >> 4, c4 = idx & 15;
            CPA16(pqb + (r * 68 + c4 * 4) * 4, qb + (size_t)r * INNERi + c4 * 4);
        }
        CP_COMMIT();
        asm volatile("cp.async.wait_group 0;");
        __syncthreads();
    }
    uint32_t qf[8][4];
#pragma unroll
    for (int kt = 0; kt < 8; kt++) {
        const float* qp = Pq + (rw + g) * 68 + kt * 8 + t;
        qf[kt][0] = FAU(qp[0]);
        qf[kt][1] = FAU(qp[8 * 68]);
        qf[kt][2] = FAU(qp[4]);
        qf[kt][3] = FAU(qp[8 * 68 + 4]);
    }
    __syncthreads();

    const float* kb = k + (size_t)b * Mm * INNERi + h * DHd;
    const float* vb = v + (size_t)b * Mm * INNERi + h * DHd;
    auto issue = [&](int mt) {
        const int s = mt & 1, m0 = mt * 64;
        const uint32_t kd = smb + s * 4352 * 4;
        const uint32_t vd = smb + (2 + s) * 4352 * 4;
#pragma unroll
        for (int p = 0; p < 8; p++) {
            int idx = tid + p * 128;
            int r = idx >> 4, c4 = idx & 15;
            CPA16(kd + (r * 68 + c4 * 4) * 4, kb + (size_t)(m0 + r) * INNERi + c4 * 4);
            CPA16(vd + (r * 68 + c4 * 4) * 4, vb + (size_t)(m0 + r) * INNERi + c4 * 4);
        }
        CP_COMMIT();
    };
    issue(0);
    issue(1);

    float o[8][4];
#pragma unroll
    for (int i = 0; i < 8; i++)
#pragma unroll
        for (int j = 0; j < 4; j++) o[i][j] = 0.f;
    float m_lo = -1e30f, m_hi = -1e30f, l_lo = 0.f, l_hi = 0.f;

    for (int mt = 0; mt < 32; mt++) {
        if (mt + 1 < 32) asm volatile("cp.async.wait_group 1;");
        else asm volatile("cp.async.wait_group 0;");
        __syncthreads();
        const float* Kc = Ks + (mt & 1) * 4352;
        const float* Vc = Vs + (mt & 1) * 4352;

        // S = Q K^T   (rows rw..rw+15, cols 0..63)
        float s[8][4];
#pragma unroll
        for (int nt = 0; nt < 8; nt++)
#pragma unroll
            for (int j = 0; j < 4; j++) s[nt][j] = 0.f;
#pragma unroll
        for (int kt = 0; kt < 8; kt++) {
#pragma unroll
            for (int nt = 0; nt < 8; nt++) {
                const float* kp = Kc + (nt * 8 + g) * 68 + kt * 8 + t;
                mma8(s[nt], qf[kt][0], qf[kt][1], qf[kt][2], qf[kt][3],
                     FAU(kp[0]), FAU(kp[4]));
            }
        }

        // scale + attn_mat
        const float* ap =
            am + ((size_t)((b * Hh + h) * Nn) + n0 + rw + g) * Mm + mt * 64 + 2 * t;
#pragma unroll
        for (int nt = 0; nt < 8; nt++) {
            float2 alo = *(const float2*)(ap + nt * 8);
            float2 ahi = *(const float2*)(ap + 8 * (size_t)Mm + nt * 8);
            s[nt][0] = s[nt][0] * sc + alo.x * mpv;
            s[nt][1] = s[nt][1] * sc + alo.y * mpv;
            s[nt][2] = s[nt][2] * sc + ahi.x * mpv;
            s[nt][3] = s[nt][3] * sc + ahi.y * mpv;
        }

        // online softmax
        float rlo = -1e30f, rhi = -1e30f;
#pragma unroll
        for (int nt = 0; nt < 8; nt++) {
            rlo = fmaxf(rlo, fmaxf(s[nt][0], s[nt][1]));
            rhi = fmaxf(rhi, fmaxf(s[nt][2], s[nt][3]));
        }
        rlo = fmaxf(rlo, __shfl_xor_sync(0xffffffffu, rlo, 1));
        rlo = fmaxf(rlo, __shfl_xor_sync(0xffffffffu, rlo, 2));
        rhi = fmaxf(rhi, __shfl_xor_sync(0xffffffffu, rhi, 1));
        rhi = fmaxf(rhi, __shfl_xor_sync(0xffffffffu, rhi, 2));
        const float mnl = fmaxf(m_lo, rlo), mnh = fmaxf(m_hi, rhi);
        const float cl = __expf(m_lo - mnl), ch = __expf(m_hi - mnh);
        m_lo = mnl;
        m_hi = mnh;
        float sl = 0.f, sh = 0.f;
#pragma unroll
        for (int nt = 0; nt < 8; nt++) {
            s[nt][0] = __expf(s[nt][0] - mnl);
            s[nt][1] = __expf(s[nt][1] - mnl);
            s[nt][2] = __expf(s[nt][2] - mnh);
            s[nt][3] = __expf(s[nt][3] - mnh);
            sl += s[nt][0] + s[nt][1];
            sh += s[nt][2] + s[nt][3];
        }
        sl += __shfl_xor_sync(0xffffffffu, sl, 1);
        sl += __shfl_xor_sync(0xffffffffu, sl, 2);
        sh += __shfl_xor_sync(0xffffffffu, sh, 1);
        sh += __shfl_xor_sync(0xffffffffu, sh, 2);
        l_lo = l_lo * cl + sl;
        l_hi = l_hi * ch + sh;

        // rescale O, write P (tf32-rounded) to warp's own rows
#pragma unroll
        for (int nt = 0; nt < 8; nt++) {
            o[nt][0] *= cl;
            o[nt][1] *= cl;
            o[nt][2] *= ch;
            o[nt][3] *= ch;
            float2 plo = {to_tf32(s[nt][0]), to_tf32(s[nt][1])};
            float2 phi = {to_tf32(s[nt][2]), to_tf32(s[nt][3])};
            *(float2*)(Pq + (rw + g) * 68 + nt * 8 + 2 * t) = plo;
            *(float2*)(Pq + (rw + g + 8) * 68 + nt * 8 + 2 * t) = phi;
        }
        __syncwarp();

        // O += P V
#pragma unroll
        for (int kt = 0; kt < 8; kt++) {
            const float* pp = Pq + (rw + g) * 68 + kt * 8 + t;
            const uint32_t pa0 = FAU(pp[0]), pa1 = FAU(pp[8 * 68]);
            const uint32_t pa2 = FAU(pp[4]), pa3 = FAU(pp[8 * 68 + 4]);
#pragma unroll
            for (int nt = 0; nt < 8; nt++) {
                const float* vp = Vc + (kt * 8 + t) * 68 + nt * 8 + g;
                mma8(o[nt], pa0, pa1, pa2, pa3, FAU(vp[0]), FAU(vp[4 * 68]));
            }
        }
        __syncthreads();
        if (mt + 2 < 32) issue(mt + 2);
    }

    // epilogue: ctx rows, tf32-rounded (feeds out-proj MMA)
    const float il = 1.f / l_lo, ih = 1.f / l_hi;
    float* ob = ctx + ((size_t)(b * Nn) + n0 + rw + g) * INNERi + h * DHd + 2 * t;
#pragma unroll
    for (int nt = 0; nt < 8; nt++) {
        float2 vlo = {to_tf32(o[nt][0] * il), to_tf32(o[nt][1] * il)};
        float2 vhi = {to_tf32(o[nt][2] * ih), to_tf32(o[nt][3] * ih)};
        *(float2*)(ob + nt * 8) = vlo;
        *(float2*)(ob + 8 * (size_t)INNERi + nt * 8) = vhi;
    }
}

extern "C" void kernel_launch(void* const* d_in, const int* in_sizes, int n_in,
                              void* d_out, int out_size) {
    const float* x = (const float*)d_in[0];
    const float* x1 = (const float*)d_in[1];
    const float* am = (const float*)d_in[2];
    const float* dp = (const float*)d_in[3];
    const float* mp = (const float*)d_in[4];
    const float* Wqv = (const float*)d_in[5];
    const float* Wk = (const float*)d_in[6];
    const float* Wout = (const float*)d_in[7];
    const float* bout = (const float*)d_in[8];
    float* out = (float*)d_out;

    float *gq, *gk, *gv, *gctx, *wqvt, *wkt, *wot;
    cudaGetSymbolAddress((void**)&gq, g_q);
    cudaGetSymbolAddress((void**)&gk, g_k);
    cudaGetSymbolAddress((void**)&gv, g_v);
    cudaGetSymbolAddress((void**)&gctx, g_ctx);
    cudaGetSymbolAddress((void**)&wqvt, g_wqvt);
    cudaGetSymbolAddress((void**)&wkt, g_wkt);
    cudaGetSymbolAddress((void**)&wot, g_wot);

    const int rows = Bb * Nn;  // 4096
    const int SM_GEMM = 2 * 9216 * 4;  // 73728
    const int SM_ATTN = 5 * 4352 * 4;  // 87040

    cudaFuncSetAttribute(mma_gemm<0>, cudaFuncAttributeMaxDynamicSharedMemorySize, SM_GEMM);
    cudaFuncSetAttribute(mma_gemm<1>, cudaFuncAttributeMaxDynamicSharedMemorySize, SM_GEMM);
    cudaFuncSetAttribute(mma_gemm<2>, cudaFuncAttributeMaxDynamicSharedMemorySize, SM_GEMM);
    cudaFuncSetAttribute(attn_mma, cudaFuncAttributeMaxDynamicSharedMemorySize, SM_ATTN);

    // prepass: transpose+round weights (single launch)
    transposeAll<<<1024, 256>>>(Wqv, Wk, Wout, wqvt, wkt, wot);

    // projections (A rounded in-kernel at fragment load)
    mma_gemm<1><<<dim3((2 * INNERi) / 128, rows / 128), 256, SM_GEMM>>>(
        x, wqvt, gq, gv, nullptr, 2 * INNERi, DIMd);
    mma_gemm<0><<<dim3(INNERi / 128, rows / 128), 256, SM_GEMM>>>(
        x1, wkt, gk, nullptr, nullptr, INNERi, DIMd);

    // fused attention: 64 q-rows per CTA, 128 threads, 2 CTAs/SM
    attn_mma<<<dim3(Nn / 64, Hh, Bb), 128, SM_ATTN>>>(gq, gk, gv, am, dp, mp, gctx);

    // output projection + bias
    mma_gemm<2><<<dim3(DIMd / 128, rows / 128), 256, SM_GEMM>>>(
        gctx, wot, out, nullptr, bout, DIMd, INNERi);
}

// round 7
// speedup vs baseline: 1.5351x; 1.5351x over previous
#include <cuda_runtime.h>
#include <cstdint>
#include <math.h>

#define Bb 2
#define Nn 2048
#define Mm 2048
#define DIMd 512
#define Hh 8
#define DHd 64
#define INNERi 512

// ---------------- scratch (allocation-free) ----------------
__device__ float g_q[Bb * Nn * INNERi];
__device__ float g_k[Bb * Mm * INNERi];
__device__ float g_v[Bb * Nn * INNERi];
__device__ float g_ctx[Bb * Nn * INNERi];
__device__ float g_wqvt[2 * INNERi * DIMd];
__device__ float g_wkt[INNERi * DIMd];
__device__ float g_wot[DIMd * INNERi];

// ---------------- helpers ----------------
__device__ __forceinline__ float to_tf32(float x) {
    uint32_t r;
    asm("cvt.rna.tf32.f32 %0, %1;" : "=r"(r) : "f"(x));
    return __uint_as_float(r);
}
__device__ __forceinline__ uint32_t to_tf32u(float x) {
    uint32_t r;
    asm("cvt.rna.tf32.f32 %0, %1;" : "=r"(r) : "f"(x));
    return r;
}
__device__ __forceinline__ void mma8(float* c, uint32_t a0, uint32_t a1,
                                     uint32_t a2, uint32_t a3, uint32_t b0,
                                     uint32_t b1) {
    asm volatile(
        "mma.sync.aligned.m16n8k8.row.col.f32.tf32.tf32.f32 "
        "{%0,%1,%2,%3}, {%4,%5,%6,%7}, {%8,%9}, {%0,%1,%2,%3};"
        : "+f"(c[0]), "+f"(c[1]), "+f"(c[2]), "+f"(c[3])
        : "r"(a0), "r"(a1), "r"(a2), "r"(a3), "r"(b0), "r"(b1));
}
#define FAU(x) __float_as_uint(x)
#define CPA16(dst, src) \
    asm volatile("cp.async.cg.shared.global [%0], [%1], 16;" ::"r"(dst), "l"(src))
#define CP_COMMIT() asm volatile("cp.async.commit_group;")

// ---------------- batched W transpose + tf32 round (one launch) ------------
__global__ __launch_bounds__(256) void transposeAll(
    const float* __restrict__ Wqv, const float* __restrict__ Wk,
    const float* __restrict__ Wout, float* __restrict__ wqvt,
    float* __restrict__ wkt, float* __restrict__ wot) {
    __shared__ float t[32][33];
    int bid = blockIdx.x;
    const float* W;
    float* Wt;
    int N, bloc;
    if (bid < 512) { W = Wqv; Wt = wqvt; N = 1024; bloc = bid; }
    else if (bid < 768) { W = Wk; Wt = wkt; N = 512; bloc = bid - 512; }
    else { W = Wout; Wt = wot; N = 512; bloc = bid - 768; }
    const int K = 512;
    int nb = N / 32;
    int n0 = (bloc % nb) * 32, k0 = (bloc / nb) * 32;
    int x = threadIdx.x & 31, y = threadIdx.x >> 5;
#pragma unroll
    for (int i = 0; i < 32; i += 8) t[y + i][x] = W[(size_t)(k0 + y + i) * N + n0 + x];
    __syncthreads();
#pragma unroll
    for (int i = 0; i < 32; i += 8)
        Wt[(size_t)(n0 + y + i) * K + k0 + x] = to_tf32(t[x][y + i]);
}

// ---------------- mma.sync tf32 GEMM (unchanged from R6) ----------------
template <int MODE>
__global__ __launch_bounds__(256) void mma_gemm(
    const float* __restrict__ A, const float* __restrict__ Wt,
    float* __restrict__ C0, float* __restrict__ C1,
    const float* __restrict__ bias, int Cols, int Kd) {
    extern __shared__ float sm[];
    const int tid = threadIdx.x, lane = tid & 31, wid = tid >> 5;
    const int g = lane >> 2, t = lane & 3;
    const int warp_m = wid & 1, warp_n = wid >> 1;
    const int row0 = blockIdx.y * 128, col0 = blockIdx.x * 128;
    const uint32_t smb = (uint32_t)__cvta_generic_to_shared(sm);

    float acc[4][4][4];
#pragma unroll
    for (int i = 0; i < 4; i++)
#pragma unroll
        for (int j = 0; j < 4; j++)
#pragma unroll
            for (int q = 0; q < 4; q++) acc[i][j][q] = 0.f;

    const int nch = Kd / 32;
    auto issue = [&](int c) {
        const int s = c & 1, k0 = c * 32;
        const uint32_t ab = smb + s * 9216 * 4;
        const uint32_t bb = ab + 4608 * 4;
#pragma unroll
        for (int p = 0; p < 4; p++) {
            int idx = tid + p * 256;
            int r = idx >> 3, c4 = idx & 7;
            CPA16(ab + (r * 36 + c4 * 4) * 4, &A[(size_t)(row0 + r) * Kd + k0 + c4 * 4]);
            CPA16(bb + (r * 36 + c4 * 4) * 4, &Wt[(size_t)(col0 + r) * Kd + k0 + c4 * 4]);
        }
        CP_COMMIT();
    };
    issue(0);
    issue(1);

    for (int c = 0; c < nch; c++) {
        if (c + 1 < nch) asm volatile("cp.async.wait_group 1;");
        else asm volatile("cp.async.wait_group 0;");
        __syncthreads();
        const float* As = sm + (c & 1) * 9216;
        const float* Bs = As + 4608;
#pragma unroll
        for (int ks = 0; ks < 4; ks++) {
            const int k0s = ks * 8;
            uint32_t af[4][4], bf[4][2];
#pragma unroll
            for (int mt = 0; mt < 4; mt++) {
                const float* ap = As + (warp_m * 64 + mt * 16 + g) * 36 + k0s + t;
                af[mt][0] = to_tf32u(ap[0]);
                af[mt][1] = to_tf32u(ap[8 * 36]);
                af[mt][2] = to_tf32u(ap[4]);
                af[mt][3] = to_tf32u(ap[8 * 36 + 4]);
            }
#pragma unroll
            for (int nt = 0; nt < 4; nt++) {
                const float* bp = Bs + (warp_n * 32 + nt * 8 + g) * 36 + k0s + t;
                bf[nt][0] = FAU(bp[0]);
                bf[nt][1] = FAU(bp[4]);
            }
#pragma unroll
            for (int mt = 0; mt < 4; mt++)
#pragma unroll
                for (int nt = 0; nt < 4; nt++)
                    mma8(acc[mt][nt], af[mt][0], af[mt][1], af[mt][2], af[mt][3],
                         bf[nt][0], bf[nt][1]);
        }
        __syncthreads();
        if (c + 2 < nch) issue(c + 2);
    }

#pragma unroll
    for (int mt = 0; mt < 4; mt++) {
#pragma unroll
        for (int nt = 0; nt < 4; nt++) {
            const int r = row0 + warp_m * 64 + mt * 16 + g;
            const int cc = col0 + warp_n * 32 + nt * 8 + 2 * t;
            float v0 = acc[mt][nt][0], v1 = acc[mt][nt][1];
            float v2 = acc[mt][nt][2], v3 = acc[mt][nt][3];
            if (MODE == 2) {
                v0 += bias[cc];
                v1 += bias[cc + 1];
                v2 += bias[cc];
                v3 += bias[cc + 1];
            } else {
                v0 = to_tf32(v0);
                v1 = to_tf32(v1);
                v2 = to_tf32(v2);
                v3 = to_tf32(v3);
            }
            float* dst = C0;
            int c2 = cc, ld = Cols;
            if (MODE == 1) {
                dst = (cc < INNERi) ? C0 : C1;
                c2 = cc & (INNERi - 1);
                ld = INNERi;
            }
            float2 lo = {v0, v1}, hi = {v2, v3};
            *(float2*)&dst[(size_t)r * ld + c2] = lo;
            *(float2*)&dst[(size_t)(r + 8) * ld + c2] = hi;
        }
    }
}

// ---------------- fused attention: 128 q-rows, 256 thr, prefetch + shuffle-P
__global__ __launch_bounds__(256) void attn_mma(
    const float* __restrict__ q, const float* __restrict__ k,
    const float* __restrict__ v, const float* __restrict__ am,
    const float* __restrict__ dp, const float* __restrict__ mp,
    float* __restrict__ ctx) {
    extern __shared__ float sm[];
    // Ks: 2 x [64][68] @ 0 ; Vs: 2 x [64][68] @ 8704 ; Qs: [128][68] @ 17408
    float* Ks = sm;
    float* Vs = sm + 2 * 4352;
    float* Qs = sm + 4 * 4352;

    const int tid = threadIdx.x, lane = tid & 31, wid = tid >> 5;
    const int g = lane >> 2, t = lane & 3;
    const int n0 = blockIdx.x * 128;
    const int h = blockIdx.y, b = blockIdx.z;
    const int rw = wid * 16;
    const float sc = 0.125f * dp[0];
    const float mpv = mp[0];
    const uint32_t smb = (uint32_t)__cvta_generic_to_shared(sm);
    const uint32_t qsb = smb + 4 * 4352 * 4;

    // stage Q tile [128][64] into Qs
    {
        const float* qb = q + ((size_t)(b * Nn) + n0) * INNERi + h * DHd;
#pragma unroll
        for (int p = 0; p < 8; p++) {
            int idx = tid + p * 256;
            int r = idx >> 4, c4 = idx & 15;
            CPA16(qsb + (r * 68 + c4 * 4) * 4, qb + (size_t)r * INNERi + c4 * 4);
        }
        CP_COMMIT();
        asm volatile("cp.async.wait_group 0;");
        __syncthreads();
    }
    uint32_t qf[8][4];
#pragma unroll
    for (int kt = 0; kt < 8; kt++) {
        const float* qp = Qs + (rw + g) * 68 + kt * 8 + t;
        qf[kt][0] = FAU(qp[0]);
        qf[kt][1] = FAU(qp[8 * 68]);
        qf[kt][2] = FAU(qp[4]);
        qf[kt][3] = FAU(qp[8 * 68 + 4]);
    }
    __syncthreads();

    const float* kb = k + (size_t)b * Mm * INNERi + h * DHd;
    const float* vb = v + (size_t)b * Mm * INNERi + h * DHd;
    auto issue = [&](int mt) {
        const int s = mt & 1, m0 = mt * 64;
        const uint32_t kd = smb + s * 4352 * 4;
        const uint32_t vd = smb + (2 + s) * 4352 * 4;
#pragma unroll
        for (int p = 0; p < 4; p++) {
            int idx = tid + p * 256;
            int r = idx >> 4, c4 = idx & 15;
            CPA16(kd + (r * 68 + c4 * 4) * 4, kb + (size_t)(m0 + r) * INNERi + c4 * 4);
            CPA16(vd + (r * 68 + c4 * 4) * 4, vb + (size_t)(m0 + r) * INNERi + c4 * 4);
        }
        CP_COMMIT();
    };
    issue(0);
    issue(1);

    float o[8][4];
#pragma unroll
    for (int i = 0; i < 8; i++)
#pragma unroll
        for (int j = 0; j < 4; j++) o[i][j] = 0.f;
    float m_lo = -1e30f, m_hi = -1e30f, l_lo = 0.f, l_hi = 0.f;

    const float* apbase =
        am + ((size_t)((b * Hh + h) * Nn) + n0 + rw + g) * Mm + 2 * t;

    for (int mt = 0; mt < 32; mt++) {
        if (mt + 1 < 32) asm volatile("cp.async.wait_group 1;");
        else asm volatile("cp.async.wait_group 0;");
        __syncthreads();
        const float* Kc = Ks + (mt & 1) * 4352;
        const float* Vc = Vs + (mt & 1) * 4352;

        // PREFETCH attn_mat for this tile (latency hidden under S-MMA below)
        float2 alo[8], ahi[8];
        {
            const float* ap = apbase + mt * 64;
#pragma unroll
            for (int nt = 0; nt < 8; nt++) {
                alo[nt] = *(const float2*)(ap + nt * 8);
                ahi[nt] = *(const float2*)(ap + 8 * (size_t)Mm + nt * 8);
            }
        }

        // S = Q K^T
        float s[8][4];
#pragma unroll
        for (int nt = 0; nt < 8; nt++)
#pragma unroll
            for (int j = 0; j < 4; j++) s[nt][j] = 0.f;
#pragma unroll
        for (int kt = 0; kt < 8; kt++) {
#pragma unroll
            for (int nt = 0; nt < 8; nt++) {
                const float* kp = Kc + (nt * 8 + g) * 68 + kt * 8 + t;
                mma8(s[nt], qf[kt][0], qf[kt][1], qf[kt][2], qf[kt][3],
                     FAU(kp[0]), FAU(kp[4]));
            }
        }

        // scale + attn_mat (already in regs)
#pragma unroll
        for (int nt = 0; nt < 8; nt++) {
            s[nt][0] = s[nt][0] * sc + alo[nt].x * mpv;
            s[nt][1] = s[nt][1] * sc + alo[nt].y * mpv;
            s[nt][2] = s[nt][2] * sc + ahi[nt].x * mpv;
            s[nt][3] = s[nt][3] * sc + ahi[nt].y * mpv;
        }

        // online softmax
        float rlo = -1e30f, rhi = -1e30f;
#pragma unroll
        for (int nt = 0; nt < 8; nt++) {
            rlo = fmaxf(rlo, fmaxf(s[nt][0], s[nt][1]));
            rhi = fmaxf(rhi, fmaxf(s[nt][2], s[nt][3]));
        }
        rlo = fmaxf(rlo, __shfl_xor_sync(0xffffffffu, rlo, 1));
        rlo = fmaxf(rlo, __shfl_xor_sync(0xffffffffu, rlo, 2));
        rhi = fmaxf(rhi, __shfl_xor_sync(0xffffffffu, rhi, 1));
        rhi = fmaxf(rhi, __shfl_xor_sync(0xffffffffu, rhi, 2));
        const float mnl = fmaxf(m_lo, rlo), mnh = fmaxf(m_hi, rhi);
        const float cl = __expf(m_lo - mnl), ch = __expf(m_hi - mnh);
        m_lo = mnl;
        m_hi = mnh;
        float sl = 0.f, sh = 0.f;
#pragma unroll
        for (int nt = 0; nt < 8; nt++) {
            s[nt][0] = __expf(s[nt][0] - mnl);
            s[nt][1] = __expf(s[nt][1] - mnl);
            s[nt][2] = __expf(s[nt][2] - mnh);
            s[nt][3] = __expf(s[nt][3] - mnh);
            sl += s[nt][0] + s[nt][1];
            sh += s[nt][2] + s[nt][3];
        }
        sl += __shfl_xor_sync(0xffffffffu, sl, 1);
        sl += __shfl_xor_sync(0xffffffffu, sl, 2);
        sh += __shfl_xor_sync(0xffffffffu, sh, 1);
        sh += __shfl_xor_sync(0xffffffffu, sh, 2);
        l_lo = l_lo * cl + sl;
        l_hi = l_hi * ch + sh;
#pragma unroll
        for (int nt = 0; nt < 8; nt++) {
            o[nt][0] *= cl;
            o[nt][1] *= cl;
            o[nt][2] *= ch;
            o[nt][3] *= ch;
        }

        // O += P V ; P built from s accumulators via shuffles (no smem)
        const int src0 = (lane & ~3) + (t >> 1);
        const int src1 = src0 + 2;
        const bool odd = t & 1;
#pragma unroll
        for (int kt = 0; kt < 8; kt++) {
            float v00 = __shfl_sync(0xffffffffu, s[kt][0], src0);
            float v01 = __shfl_sync(0xffffffffu, s[kt][1], src0);
            float v10 = __shfl_sync(0xffffffffu, s[kt][2], src0);
            float v11 = __shfl_sync(0xffffffffu, s[kt][3], src0);
            float w00 = __shfl_sync(0xffffffffu, s[kt][0], src1);
            float w01 = __shfl_sync(0xffffffffu, s[kt][1], src1);
            float w10 = __shfl_sync(0xffffffffu, s[kt][2], src1);
            float w11 = __shfl_sync(0xffffffffu, s[kt][3], src1);
            const uint32_t pa0 = to_tf32u(odd ? v01 : v00);
            const uint32_t pa1 = to_tf32u(odd ? v11 : v10);
            const uint32_t pa2 = to_tf32u(odd ? w01 : w00);
            const uint32_t pa3 = to_tf32u(odd ? w11 : w10);
#pragma unroll
            for (int nt = 0; nt < 8; nt++) {
                const float* vp = Vc + (kt * 8 + t) * 68 + nt * 8 + g;
                mma8(o[nt], pa0, pa1, pa2, pa3, FAU(vp[0]), FAU(vp[4 * 68]));
            }
        }
        __syncthreads();
        if (mt + 2 < 32) issue(mt + 2);
    }

    // epilogue: ctx rows, tf32-rounded (feeds out-proj MMA)
    const float il = 1.f / l_lo, ih = 1.f / l_hi;
    float* ob = ctx + ((size_t)(b * Nn) + n0 + rw + g) * INNERi + h * DHd + 2 * t;
#pragma unroll
    for (int nt = 0; nt < 8; nt++) {
        float2 vlo = {to_tf32(o[nt][0] * il), to_tf32(o[nt][1] * il)};
        float2 vhi = {to_tf32(o[nt][2] * ih), to_tf32(o[nt][3] * ih)};
        *(float2*)(ob + nt * 8) = vlo;
        *(float2*)(ob + 8 * (size_t)INNERi + nt * 8) = vhi;
    }
}

extern "C" void kernel_launch(void* const* d_in, const int* in_sizes, int n_in,
                              void* d_out, int out_size) {
    const float* x = (const float*)d_in[0];
    const float* x1 = (const float*)d_in[1];
    const float* am = (const float*)d_in[2];
    const float* dp = (const float*)d_in[3];
    const float* mp = (const float*)d_in[4];
    const float* Wqv = (const float*)d_in[5];
    const float* Wk = (const float*)d_in[6];
    const float* Wout = (const float*)d_in[7];
    const float* bout = (const float*)d_in[8];
    float* out = (float*)d_out;

    float *gq, *gk, *gv, *gctx, *wqvt, *wkt, *wot;
    cudaGetSymbolAddress((void**)&gq, g_q);
    cudaGetSymbolAddress((void**)&gk, g_k);
    cudaGetSymbolAddress((void**)&gv, g_v);
    cudaGetSymbolAddress((void**)&gctx, g_ctx);
    cudaGetSymbolAddress((void**)&wqvt, g_wqvt);
    cudaGetSymbolAddress((void**)&wkt, g_wkt);
    cudaGetSymbolAddress((void**)&wot, g_wot);

    const int rows = Bb * Nn;  // 4096
    const int SM_GEMM = 2 * 9216 * 4;  // 73728
    const int SM_ATTN = 6 * 4352 * 4;  // 104448

    cudaFuncSetAttribute(mma_gemm<0>, cudaFuncAttributeMaxDynamicSharedMemorySize, SM_GEMM);
    cudaFuncSetAttribute(mma_gemm<1>, cudaFuncAttributeMaxDynamicSharedMemorySize, SM_GEMM);
    cudaFuncSetAttribute(mma_gemm<2>, cudaFuncAttributeMaxDynamicSharedMemorySize, SM_GEMM);
    cudaFuncSetAttribute(attn_mma, cudaFuncAttributeMaxDynamicSharedMemorySize, SM_ATTN);

    // prepass: transpose+round weights (single launch)
    transposeAll<<<1024, 256>>>(Wqv, Wk, Wout, wqvt, wkt, wot);

    // projections (A rounded in-kernel at fragment load)
    mma_gemm<1><<<dim3((2 * INNERi) / 128, rows / 128), 256, SM_GEMM>>>(
        x, wqvt, gq, gv, nullptr, 2 * INNERi, DIMd);
    mma_gemm<0><<<dim3(INNERi / 128, rows / 128), 256, SM_GEMM>>>(
        x1, wkt, gk, nullptr, nullptr, INNERi, DIMd);

    // fused attention: 128 q-rows per CTA, 256 threads
    attn_mma<<<dim3(Nn / 128, Hh, Bb), 256, SM_ATTN>>>(gq, gk, gv, am, dp, mp, gctx);

    // output projection + bias
    mma_gemm<2><<<dim3(DIMd / 128, rows / 128), 256, SM_GEMM>>>(
        gctx, wot, out, nullptr, bout, DIMd, INNERi);
}